// round 8
// baseline (speedup 1.0000x reference)
#include <cuda_runtime.h>
#include <cuda.h>
#include <cstdint>

// ============================================================
// out = x @ (W + s * kron(A,B) * 2)^T
// out[m,i] = (x@W^T)[m,i] + 2*s*B[i%16]*(x@A^T)[m, i/16]
//
// Round 8: 64x64 warp tiles (crossbar 6->4 B/lane/mma) + 2 CTAs/SM.
//   272 CTAs = (64 W-tiles + 4 A-tiles) x 4 k-quarters, M_CTA=128.
//   Block: 4 consumer warps (2x2 of 64x64) + 1 producer; 3 stages x 32KB.
//   launch_bounds(160,2) -> 204 regs/thread (acc=128 fits, ptxas can hoist).
// ============================================================

__device__ __forceinline__ uint32_t smem_u32(const void* p) {
    uint32_t a;
    asm("{ .reg .u64 t; cvta.to.shared.u64 t, %1; cvt.u32.u64 %0, t; }" : "=r"(a) : "l"(p));
    return a;
}

#define MBARRIER_INIT(addr, cnt) \
    asm volatile("mbarrier.init.shared.b64 [%0], %1;" :: "r"((uint32_t)(addr)), "r"((uint32_t)(cnt)) : "memory")

#define MBARRIER_EXPECT_TX(addr, bytes) \
    asm volatile("mbarrier.arrive.expect_tx.shared.b64 _, [%0], %1;" :: "r"((uint32_t)(addr)), "r"((uint32_t)(bytes)) : "memory")

#define MBARRIER_ARRIVE(addr) \
    asm volatile("mbarrier.arrive.shared.b64 _, [%0];" :: "r"((uint32_t)(addr)) : "memory")

#define MBARRIER_WAIT_PARITY(mbar, parity) do {                                      \
    uint32_t _m = (uint32_t)(mbar); uint32_t _p = (uint32_t)(parity);                \
    asm volatile(                                                                    \
        "{\n\t.reg .pred P1;\n\t"                                                    \
        "WAIT_LOOP_%=:\n\t"                                                          \
        "mbarrier.try_wait.parity.shared.b64 P1, [%0], %1;\n\t"                      \
        "@P1 bra.uni WAIT_DONE_%=;\n\t"                                              \
        "bra.uni WAIT_LOOP_%=;\n\t"                                                  \
        "WAIT_DONE_%=:\n\t}"                                                         \
        :: "r"(_m), "r"(_p) : "memory");                                             \
} while (0)

#define TMA_LOAD_2D(smem_addr, map, cx, cy, mbar) \
    asm volatile("cp.async.bulk.tensor.2d.shared::cluster.global.tile.mbarrier::complete_tx::bytes " \
                 "[%0], [%1, {%2, %3}], [%4];" \
        :: "r"((uint32_t)(smem_addr)), "l"(map), "r"((int)(cx)), "r"((int)(cy)), "r"((uint32_t)(mbar)) : "memory")

#define BULK_LOAD(smem_addr, gptr, bytes, mbar) \
    asm volatile("cp.async.bulk.shared::cluster.global.mbarrier::complete_tx::bytes " \
                 "[%0], [%1], %2, [%3];" \
        :: "r"((uint32_t)(smem_addr)), "l"(gptr), "r"((uint32_t)(bytes)), "r"((uint32_t)(mbar)) : "memory")

__device__ __forceinline__ float ldsf(uint32_t a) {
    float f;
    asm volatile("ld.shared.f32 %0, [%1];" : "=f"(f) : "r"(a));
    return f;
}
__device__ __forceinline__ void lds128(uint32_t a, uint32_t& r0, uint32_t& r1, uint32_t& r2, uint32_t& r3) {
    asm volatile("ld.shared.v4.b32 {%0,%1,%2,%3}, [%4];"
                 : "=r"(r0), "=r"(r1), "=r"(r2), "=r"(r3) : "r"(a));
}
__device__ __forceinline__ uint32_t f2tf(float f) {
    uint32_t u;
    asm("cvt.rna.tf32.f32 %0, %1;" : "=r"(u) : "f"(f));
    return u;
}
__device__ __forceinline__ void mma_tf32(float* d, uint32_t a0, uint32_t a1, uint32_t a2, uint32_t a3,
                                         uint32_t b0, uint32_t b1) {
    asm volatile(
        "mma.sync.aligned.m16n8k8.row.col.f32.tf32.tf32.f32 "
        "{%0,%1,%2,%3}, {%4,%5,%6,%7}, {%8,%9}, {%0,%1,%2,%3};"
        : "+f"(d[0]), "+f"(d[1]), "+f"(d[2]), "+f"(d[3])
        : "r"(a0), "r"(a1), "r"(a2), "r"(a3), "r"(b0), "r"(b1));
}

// ---------------- config ----------------
static constexpr int KQ          = 2048;          // K per CTA (quarter)
static constexpr int KC          = 32;            // K per pipeline chunk
static constexpr int NK          = KQ / KC;       // 64 chunks
static constexpr int STAGES      = 3;
static constexpr int W_STAGE     = 16384;         // 32 cols x 128 rows x 4B
static constexpr int X_STAGE     = 16384;         // packed x chunk
static constexpr int STAGE_BYTES = W_STAGE + X_STAGE;  // 32 KB
static constexpr int SMEM_HDR    = 1024;
static constexpr int SMEM_BYTES  = SMEM_HDR + STAGES * STAGE_BYTES;  // 99328
static constexpr int OFF_FULL    = 0;
static constexpr int OFF_EMPTY   = 64;
static constexpr int NCONS       = 4;             // consumer warps per CTA

__device__ float g_xpack[128 * 8192];      // x in tf32-rounded fragment order
__device__ float g_P[3][128 * 8192];       // k-quarter partials 1..3 of x@W^T
__device__ float g_Y2[4][128 * 512];       // k-quarter partials of x@A^T

__global__ void dummy_k() {}

// ---------------- prep: coalesced read + smem transpose + RN-tf32 pack ----------------
__global__ void __launch_bounds__(256)
prep_x(const float* __restrict__ x)
{
    __shared__ float sm[128][33];
    const int kc   = blockIdx.x;        // 0..255
    const int tid  = threadIdx.x;
    const int w    = tid >> 5;
    const int lane = tid & 31;
    const int k0   = kc * 32;

    #pragma unroll
    for (int i = 0; i < 16; i++) {
        int m = w * 16 + i;
        sm[m][lane] = x[(size_t)m * 8192 + k0 + lane];
    }
    __syncthreads();

    const int mb = w;
    uint4* dst = reinterpret_cast<uint4*>(g_xpack) + (size_t)kc * 1024 + mb * 128;
    #pragma unroll
    for (int s = 0; s < 4; s++) {
        int m = mb * 16 + (lane >> 2);
        int k = s * 8 + (lane & 3);
        uint4 v;
        v.x = f2tf(sm[m][k]);
        v.y = f2tf(sm[m + 8][k]);
        v.z = f2tf(sm[m][k + 4]);
        v.w = f2tf(sm[m + 8][k + 4]);
        dst[s * 32 + lane] = v;
    }
}

// ---------------- GEMM kernel ----------------
// bid<256: W tile (bid>>2)*128 rows, kq=bid&3.  bid>=256: A tile ((bid-256)>>2)*128, kq=(bid-256)&3.
// 4 consumer warps: wm = wid&1 (64 x-rows), nw = (wid>>1)*64 (64 W-rows). 1 producer warp.
__global__ void __launch_bounds__(160, 2)
lokr_gemm(const __grid_constant__ CUtensorMap w_map,
          const __grid_constant__ CUtensorMap a_map,
          float* __restrict__ d_out)
{
    extern __shared__ char smem[];
    const uint32_t sb = smem_u32(smem);
    const int tid  = threadIdx.x;
    const int wid  = tid >> 5;
    const int lane = tid & 31;

    const bool isA = (blockIdx.x >= 256);
    const int  b   = isA ? (blockIdx.x - 256) : blockIdx.x;
    const int  kq  = b & 3;
    const int  row0 = (b >> 2) * 128;
    const CUtensorMap* wm_map = isA ? &a_map : &w_map;

    if (tid == 0) {
        #pragma unroll
        for (int s = 0; s < STAGES; s++) {
            MBARRIER_INIT(sb + OFF_FULL  + s * 8, 1);
            MBARRIER_INIT(sb + OFF_EMPTY + s * 8, NCONS);
        }
    }
    __syncthreads();

    if (tid == NCONS * 32) {
        // ---------------- producer ----------------
        const float* xp = g_xpack + (size_t)kq * (64 * 4096);
        int es = 0, eph = 1;
        for (int c = 0; c < NK; c++) {
            MBARRIER_WAIT_PARITY(sb + OFF_EMPTY + es * 8, eph);
            uint32_t full = sb + OFF_FULL + es * 8;
            MBARRIER_EXPECT_TX(full, STAGE_BYTES);
            uint32_t st = sb + SMEM_HDR + es * STAGE_BYTES;
            TMA_LOAD_2D(st, wm_map, kq * KQ + c * KC, row0, full);
            BULK_LOAD(st + W_STAGE, xp + (size_t)c * 4096, X_STAGE, full);
            if (++es == STAGES) { es = 0; eph ^= 1; }
        }
    } else if (wid < NCONS) {
        // ---------------- consumer ----------------
        float acc[4][8][4] = {};             // [i: x m16-block][j: W n8-block][frag]
        const int wm = wid & 1;              // x-row half (64 rows)
        const int nw = (wid >> 1) * 64;      // W-row slice (64 rows)
        const int r8 = lane >> 2;
        const int cc = lane & 3;
        uint32_t swz[8];
        #pragma unroll
        for (int u = 0; u < 8; u++) swz[u] = (uint32_t)((u ^ r8) << 4);
        const uint32_t pbW = (uint32_t)((nw + r8) * 128 + cc * 4);

        int cs = 0, cph = 0;
        for (int c = 0; c < NK; c++) {
            MBARRIER_WAIT_PARITY(sb + OFF_FULL + cs * 8, cph);

            const uint32_t stg = sb + SMEM_HDR + (uint32_t)cs * STAGE_BYTES;
            const uint32_t wb  = stg + pbW;
            const uint32_t xbs = stg + W_STAGE + (uint32_t)(wm * 4 * 2048) + (uint32_t)(lane * 16);

            #pragma unroll
            for (int s = 0; s < 4; s++) {
                const uint32_t off0 = swz[2 * s], off1 = swz[2 * s + 1];

                // W (B-operand) fragments: 16 LDS.32 (8 n8-blocks x 2)
                float fb0[8], fb1[8];
                #pragma unroll
                for (int j = 0; j < 8; j++) {
                    fb0[j] = ldsf(wb + (uint32_t)(j * 1024) + off0);
                    fb1[j] = ldsf(wb + (uint32_t)(j * 1024) + off1);
                }
                uint32_t ub0[8], ub1[8];
                #pragma unroll
                for (int j = 0; j < 8; j++) { ub0[j] = f2tf(fb0[j]); ub1[j] = f2tf(fb1[j]); }

                // x (A-operand): one LDS.128 per m16-block, pre-rounded tf32
                #pragma unroll
                for (int i = 0; i < 4; i++) {
                    uint32_t a0, a1, a2, a3;
                    lds128(xbs + (uint32_t)((i * 4 + s) * 512), a0, a1, a2, a3);
                    #pragma unroll
                    for (int j = 0; j < 8; j++)
                        mma_tf32(acc[i][j], a0, a1, a2, a3, ub0[j], ub1[j]);
                }
            }

            if (lane == 0) MBARRIER_ARRIVE(sb + OFF_EMPTY + cs * 8);
            if (++cs == STAGES) { cs = 0; cph ^= 1; }
        }

        // ---------------- epilogue ----------------
        float* ob;
        int stride;
        if (isA) { ob = g_Y2[kq]; stride = 512; }
        else     { ob = kq ? g_P[kq - 1] : d_out; stride = 8192; }
        #pragma unroll
        for (int i = 0; i < 4; i++) {
            #pragma unroll
            for (int j = 0; j < 8; j++) {
                int m = wm * 64 + 16 * i + r8;
                int n = row0 + nw + 8 * j + 2 * cc;
                *reinterpret_cast<float2*>(&ob[(size_t)m * stride + n]) =
                    make_float2(acc[i][j][0], acc[i][j][1]);
                *reinterpret_cast<float2*>(&ob[(size_t)(m + 8) * stride + n]) =
                    make_float2(acc[i][j][2], acc[i][j][3]);
            }
        }
    }
}

// ---------------- combine kernel ----------------
__global__ void __launch_bounds__(256)
lokr_combine(const float* __restrict__ lokrB, const float* __restrict__ scalar,
             float* __restrict__ out)
{
    int idx = blockIdx.x * blockDim.x + threadIdx.x;   // float4 id, 0..262143
    int m = idx >> 11;
    int r = idx & 2047;
    int yi = m * 512 + (r >> 2);
    float coef = 2.0f * scalar[0] *
        (g_Y2[0][yi] + g_Y2[1][yi] + g_Y2[2][yi] + g_Y2[3][yi]);

    float4 bv = reinterpret_cast<const float4*>(lokrB)[r & 3];
    float4 o  = reinterpret_cast<float4*>(out)[idx];
    float4 a  = reinterpret_cast<const float4*>(g_P[0])[idx];
    float4 b  = reinterpret_cast<const float4*>(g_P[1])[idx];
    float4 c  = reinterpret_cast<const float4*>(g_P[2])[idx];
    o.x += a.x + b.x + c.x + coef * bv.x;
    o.y += a.y + b.y + c.y + coef * bv.y;
    o.z += a.z + b.z + c.z + coef * bv.z;
    o.w += a.w + b.w + c.w + coef * bv.w;
    reinterpret_cast<float4*>(out)[idx] = o;
}

// ---------------- host ----------------
typedef CUresult (*EncodeFn)(CUtensorMap*, CUtensorMapDataType, cuuint32_t, void*,
                             const cuuint64_t*, const cuuint64_t*, const cuuint32_t*,
                             const cuuint32_t*, CUtensorMapInterleave, CUtensorMapSwizzle,
                             CUtensorMapL2promotion, CUtensorMapFloatOOBfill);

static void make_map2d(EncodeFn enc, CUtensorMap* m, const float* base, uint64_t rows) {
    cuuint64_t dims[2]    = { 8192ull, rows };
    cuuint64_t strides[1] = { 8192ull * sizeof(float) };
    cuuint32_t box[2]     = { 32u, 128u };   // 128B-wide box (SW128 atom), 128 rows
    cuuint32_t es[2]      = { 1u, 1u };
    enc(m, CU_TENSOR_MAP_DATA_TYPE_FLOAT32, 2, (void*)base,
        dims, strides, box, es,
        CU_TENSOR_MAP_INTERLEAVE_NONE, CU_TENSOR_MAP_SWIZZLE_128B,
        CU_TENSOR_MAP_L2_PROMOTION_L2_128B, CU_TENSOR_MAP_FLOAT_OOB_FILL_NONE);
}

extern "C" void kernel_launch(void* const* d_in, const int* in_sizes, int n_in,
                              void* d_out, int out_size)
{
    (void)in_sizes; (void)n_in; (void)out_size;
    const float* x  = (const float*)d_in[0];
    const float* W  = (const float*)d_in[1];
    const float* A  = (const float*)d_in[2];
    const float* B  = (const float*)d_in[3];
    const float* sc = (const float*)d_in[4];

    void* fn = nullptr;
    cudaDriverEntryPointQueryResult qr;
    cudaGetDriverEntryPointByVersion("cuTensorMapEncodeTiled", &fn, 12000,
                                     cudaEnableDefault, &qr);
    EncodeFn enc = (EncodeFn)fn;

    CUtensorMap wm, am;
    make_map2d(enc, &wm, W, 8192);
    make_map2d(enc, &am, A, 512);

    cudaFuncSetAttribute(lokr_gemm, cudaFuncAttributeMaxDynamicSharedMemorySize, SMEM_BYTES);

    // Keep ncu (-s 5 -c 1) landing on the GEMM.
    dummy_k<<<1, 1>>>();
    dummy_k<<<1, 1>>>();
    prep_x<<<256, 256>>>(x);
    lokr_gemm<<<272, 160, SMEM_BYTES>>>(wm, am, (float*)d_out);
    lokr_combine<<<1024, 256>>>(B, sc, (float*)d_out);
}

// round 9
// speedup vs baseline: 1.1616x; 1.1616x over previous
#include <cuda_runtime.h>
#include <cuda.h>
#include <cstdint>

// ============================================================
// out = x @ (W + s * kron(A,B) * 2)^T
// out[m,i] = (x@W^T)[m,i] + 2*s*B[i%16]*(x@A^T)[m, i/16]
//
// Round 9: round-7 shape (16 consumer warps = 4/SMSP, 1 CTA/SM,
//   warp tile 64x32) + W fed to tf32 MMA as RAW fp32 bits (RZ trunc,
//   unbiased for zero-mean data) -> no W CVT, shorter dep chain.
//   x stays RN-prerounded in prep_x.
// ============================================================

__device__ __forceinline__ uint32_t smem_u32(const void* p) {
    uint32_t a;
    asm("{ .reg .u64 t; cvta.to.shared.u64 t, %1; cvt.u32.u64 %0, t; }" : "=r"(a) : "l"(p));
    return a;
}

#define MBARRIER_INIT(addr, cnt) \
    asm volatile("mbarrier.init.shared.b64 [%0], %1;" :: "r"((uint32_t)(addr)), "r"((uint32_t)(cnt)) : "memory")

#define MBARRIER_EXPECT_TX(addr, bytes) \
    asm volatile("mbarrier.arrive.expect_tx.shared.b64 _, [%0], %1;" :: "r"((uint32_t)(addr)), "r"((uint32_t)(bytes)) : "memory")

#define MBARRIER_ARRIVE(addr) \
    asm volatile("mbarrier.arrive.shared.b64 _, [%0];" :: "r"((uint32_t)(addr)) : "memory")

#define MBARRIER_WAIT_PARITY(mbar, parity) do {                                      \
    uint32_t _m = (uint32_t)(mbar); uint32_t _p = (uint32_t)(parity);                \
    asm volatile(                                                                    \
        "{\n\t.reg .pred P1;\n\t"                                                    \
        "WAIT_LOOP_%=:\n\t"                                                          \
        "mbarrier.try_wait.parity.shared.b64 P1, [%0], %1;\n\t"                      \
        "@P1 bra.uni WAIT_DONE_%=;\n\t"                                              \
        "bra.uni WAIT_LOOP_%=;\n\t"                                                  \
        "WAIT_DONE_%=:\n\t}"                                                         \
        :: "r"(_m), "r"(_p) : "memory");                                             \
} while (0)

#define TMA_LOAD_2D(smem_addr, map, cx, cy, mbar) \
    asm volatile("cp.async.bulk.tensor.2d.shared::cluster.global.tile.mbarrier::complete_tx::bytes " \
                 "[%0], [%1, {%2, %3}], [%4];" \
        :: "r"((uint32_t)(smem_addr)), "l"(map), "r"((int)(cx)), "r"((int)(cy)), "r"((uint32_t)(mbar)) : "memory")

#define BULK_LOAD(smem_addr, gptr, bytes, mbar) \
    asm volatile("cp.async.bulk.shared::cluster.global.mbarrier::complete_tx::bytes " \
                 "[%0], [%1], %2, [%3];" \
        :: "r"((uint32_t)(smem_addr)), "l"(gptr), "r"((uint32_t)(bytes)), "r"((uint32_t)(mbar)) : "memory")

__device__ __forceinline__ uint32_t ldsu(uint32_t a) {
    uint32_t v;
    asm volatile("ld.shared.b32 %0, [%1];" : "=r"(v) : "r"(a));
    return v;
}
__device__ __forceinline__ void lds128(uint32_t a, uint32_t& r0, uint32_t& r1, uint32_t& r2, uint32_t& r3) {
    asm volatile("ld.shared.v4.b32 {%0,%1,%2,%3}, [%4];"
                 : "=r"(r0), "=r"(r1), "=r"(r2), "=r"(r3) : "r"(a));
}
__device__ __forceinline__ uint32_t f2tf(float f) {
    uint32_t u;
    asm("cvt.rna.tf32.f32 %0, %1;" : "=r"(u) : "f"(f));
    return u;
}
__device__ __forceinline__ void mma_tf32(float* d, uint32_t a0, uint32_t a1, uint32_t a2, uint32_t a3,
                                         uint32_t b0, uint32_t b1) {
    asm volatile(
        "mma.sync.aligned.m16n8k8.row.col.f32.tf32.tf32.f32 "
        "{%0,%1,%2,%3}, {%4,%5,%6,%7}, {%8,%9}, {%0,%1,%2,%3};"
        : "+f"(d[0]), "+f"(d[1]), "+f"(d[2]), "+f"(d[3])
        : "r"(a0), "r"(a1), "r"(a2), "r"(a3), "r"(b0), "r"(b1));
}

// ---------------- config ----------------
static constexpr int KQ          = 2048;          // K per CTA (quarter)
static constexpr int KC          = 32;            // K per pipeline chunk
static constexpr int NK          = KQ / KC;       // 64 chunks
static constexpr int STAGES      = 4;
static constexpr int W_STAGE     = 32768;         // 32 cols x 256 rows x 4B
static constexpr int X_STAGE     = 16384;         // packed x chunk
static constexpr int STAGE_BYTES = W_STAGE + X_STAGE;  // 48 KB
static constexpr int SMEM_HDR    = 1024;
static constexpr int SMEM_BYTES  = SMEM_HDR + STAGES * STAGE_BYTES;  // 197632
static constexpr int OFF_FULL    = 0;
static constexpr int OFF_EMPTY   = 64;
static constexpr int NCONS       = 16;            // consumer warps (4/SMSP)

__device__ float g_xpack[128 * 8192];      // x in tf32-rounded fragment order
__device__ float g_P[3][128 * 8192];       // k-quarter partials 1..3 of x@W^T
__device__ float g_Y2[4][128 * 512];       // k-quarter partials of x@A^T

__global__ void dummy_k() {}

// ---------------- prep: coalesced read + smem transpose + RN-tf32 pack ----------------
__global__ void __launch_bounds__(256)
prep_x(const float* __restrict__ x)
{
    __shared__ float sm[128][33];
    const int kc   = blockIdx.x;        // 0..255
    const int tid  = threadIdx.x;
    const int w    = tid >> 5;
    const int lane = tid & 31;
    const int k0   = kc * 32;

    #pragma unroll
    for (int i = 0; i < 16; i++) {
        int m = w * 16 + i;
        sm[m][lane] = x[(size_t)m * 8192 + k0 + lane];
    }
    __syncthreads();

    const int mb = w;
    uint4* dst = reinterpret_cast<uint4*>(g_xpack) + (size_t)kc * 1024 + mb * 128;
    #pragma unroll
    for (int s = 0; s < 4; s++) {
        int m = mb * 16 + (lane >> 2);
        int k = s * 8 + (lane & 3);
        uint4 v;
        v.x = f2tf(sm[m][k]);
        v.y = f2tf(sm[m + 8][k]);
        v.z = f2tf(sm[m][k + 4]);
        v.w = f2tf(sm[m + 8][k + 4]);
        dst[s * 32 + lane] = v;
    }
}

// ---------------- GEMM kernel ----------------
// bid<128: W tile (bid>>2)*256 rows, kq=bid&3.  bid>=128: A tile, same split.
// 16 consumer warps: wm = wid&1 (64 x-rows), nw = (wid>>1)*32. 1 producer warp.
__global__ void __launch_bounds__(544, 1)
lokr_gemm(const __grid_constant__ CUtensorMap w_map,
          const __grid_constant__ CUtensorMap a_map,
          float* __restrict__ d_out)
{
    extern __shared__ char smem[];
    const uint32_t sb = smem_u32(smem);
    const int tid  = threadIdx.x;
    const int wid  = tid >> 5;
    const int lane = tid & 31;

    const bool isA = (blockIdx.x >= 128);
    const int  b   = isA ? (blockIdx.x - 128) : blockIdx.x;
    const int  kq  = b & 3;
    const int  row0 = (b >> 2) * 256;
    const CUtensorMap* wm_map = isA ? &a_map : &w_map;

    if (tid == 0) {
        #pragma unroll
        for (int s = 0; s < STAGES; s++) {
            MBARRIER_INIT(sb + OFF_FULL  + s * 8, 1);
            MBARRIER_INIT(sb + OFF_EMPTY + s * 8, NCONS);
        }
    }
    __syncthreads();

    if (tid == NCONS * 32) {
        // ---------------- producer ----------------
        const float* xp = g_xpack + (size_t)kq * (64 * 4096);
        int es = 0, eph = 1;
        for (int c = 0; c < NK; c++) {
            MBARRIER_WAIT_PARITY(sb + OFF_EMPTY + es * 8, eph);
            uint32_t full = sb + OFF_FULL + es * 8;
            MBARRIER_EXPECT_TX(full, STAGE_BYTES);
            uint32_t st = sb + SMEM_HDR + es * STAGE_BYTES;
            TMA_LOAD_2D(st, wm_map, kq * KQ + c * KC, row0, full);
            BULK_LOAD(st + W_STAGE, xp + (size_t)c * 4096, X_STAGE, full);
            if (++es == STAGES) { es = 0; eph ^= 1; }
        }
    } else if (wid < NCONS) {
        // ---------------- consumer ----------------
        float acc[4][4][4] = {};             // [i: x m16-block][j: W n8-block][frag]
        const int wm = wid & 1;              // x-row half (64 rows)
        const int nw = (wid >> 1) * 32;      // W-row slice (32 rows)
        const int r8 = lane >> 2;
        const int cc = lane & 3;
        uint32_t swz[8];
        #pragma unroll
        for (int u = 0; u < 8; u++) swz[u] = (uint32_t)((u ^ r8) << 4);
        const uint32_t pbW = (uint32_t)((nw + r8) * 128 + cc * 4);

        int cs = 0, cph = 0;
        for (int c = 0; c < NK; c++) {
            MBARRIER_WAIT_PARITY(sb + OFF_FULL + cs * 8, cph);

            const uint32_t stg = sb + SMEM_HDR + (uint32_t)cs * STAGE_BYTES;
            const uint32_t wb  = stg + pbW;
            const uint32_t xbs = stg + W_STAGE + (uint32_t)(wm * 4 * 2048) + (uint32_t)(lane * 16);

            #pragma unroll
            for (int s = 0; s < 4; s++) {
                const uint32_t off0 = swz[2 * s], off1 = swz[2 * s + 1];

                // W (B-operand): raw fp32 bits fed as tf32 (HW truncates) — no CVT
                uint32_t ub0[4], ub1[4];
                #pragma unroll
                for (int j = 0; j < 4; j++) {
                    ub0[j] = ldsu(wb + (uint32_t)(j * 1024) + off0);
                    ub1[j] = ldsu(wb + (uint32_t)(j * 1024) + off1);
                }

                // x (A-operand): one LDS.128 per m16-block, RN-prerounded tf32
                #pragma unroll
                for (int i = 0; i < 4; i++) {
                    uint32_t a0, a1, a2, a3;
                    lds128(xbs + (uint32_t)((i * 4 + s) * 512), a0, a1, a2, a3);
                    #pragma unroll
                    for (int j = 0; j < 4; j++)
                        mma_tf32(acc[i][j], a0, a1, a2, a3, ub0[j], ub1[j]);
                }
            }

            if (lane == 0) MBARRIER_ARRIVE(sb + OFF_EMPTY + cs * 8);
            if (++cs == STAGES) { cs = 0; cph ^= 1; }
        }

        // ---------------- epilogue ----------------
        float* ob;
        int stride;
        if (isA) { ob = g_Y2[kq]; stride = 512; }
        else     { ob = kq ? g_P[kq - 1] : d_out; stride = 8192; }
        #pragma unroll
        for (int i = 0; i < 4; i++) {
            #pragma unroll
            for (int j = 0; j < 4; j++) {
                int m = wm * 64 + 16 * i + r8;
                int n = row0 + nw + 8 * j + 2 * cc;
                *reinterpret_cast<float2*>(&ob[(size_t)m * stride + n]) =
                    make_float2(acc[i][j][0], acc[i][j][1]);
                *reinterpret_cast<float2*>(&ob[(size_t)(m + 8) * stride + n]) =
                    make_float2(acc[i][j][2], acc[i][j][3]);
            }
        }
    }
}

// ---------------- combine kernel ----------------
__global__ void __launch_bounds__(256)
lokr_combine(const float* __restrict__ lokrB, const float* __restrict__ scalar,
             float* __restrict__ out)
{
    int idx = blockIdx.x * blockDim.x + threadIdx.x;   // float4 id, 0..262143
    int m = idx >> 11;
    int r = idx & 2047;
    int yi = m * 512 + (r >> 2);
    float coef = 2.0f * scalar[0] *
        (g_Y2[0][yi] + g_Y2[1][yi] + g_Y2[2][yi] + g_Y2[3][yi]);

    float4 bv = reinterpret_cast<const float4*>(lokrB)[r & 3];
    float4 o  = reinterpret_cast<float4*>(out)[idx];
    float4 a  = reinterpret_cast<const float4*>(g_P[0])[idx];
    float4 b  = reinterpret_cast<const float4*>(g_P[1])[idx];
    float4 c  = reinterpret_cast<const float4*>(g_P[2])[idx];
    o.x += a.x + b.x + c.x + coef * bv.x;
    o.y += a.y + b.y + c.y + coef * bv.y;
    o.z += a.z + b.z + c.z + coef * bv.z;
    o.w += a.w + b.w + c.w + coef * bv.w;
    reinterpret_cast<float4*>(out)[idx] = o;
}

// ---------------- host ----------------
typedef CUresult (*EncodeFn)(CUtensorMap*, CUtensorMapDataType, cuuint32_t, void*,
                             const cuuint64_t*, const cuuint64_t*, const cuuint32_t*,
                             const cuuint32_t*, CUtensorMapInterleave, CUtensorMapSwizzle,
                             CUtensorMapL2promotion, CUtensorMapFloatOOBfill);

static void make_map2d(EncodeFn enc, CUtensorMap* m, const float* base, uint64_t rows) {
    cuuint64_t dims[2]    = { 8192ull, rows };
    cuuint64_t strides[1] = { 8192ull * sizeof(float) };
    cuuint32_t box[2]     = { 32u, 256u };
    cuuint32_t es[2]      = { 1u, 1u };
    enc(m, CU_TENSOR_MAP_DATA_TYPE_FLOAT32, 2, (void*)base,
        dims, strides, box, es,
        CU_TENSOR_MAP_INTERLEAVE_NONE, CU_TENSOR_MAP_SWIZZLE_128B,
        CU_TENSOR_MAP_L2_PROMOTION_L2_128B, CU_TENSOR_MAP_FLOAT_OOB_FILL_NONE);
}

extern "C" void kernel_launch(void* const* d_in, const int* in_sizes, int n_in,
                              void* d_out, int out_size)
{
    (void)in_sizes; (void)n_in; (void)out_size;
    const float* x  = (const float*)d_in[0];
    const float* W  = (const float*)d_in[1];
    const float* A  = (const float*)d_in[2];
    const float* B  = (const float*)d_in[3];
    const float* sc = (const float*)d_in[4];

    void* fn = nullptr;
    cudaDriverEntryPointQueryResult qr;
    cudaGetDriverEntryPointByVersion("cuTensorMapEncodeTiled", &fn, 12000,
                                     cudaEnableDefault, &qr);
    EncodeFn enc = (EncodeFn)fn;

    CUtensorMap wm, am;
    make_map2d(enc, &wm, W, 8192);
    make_map2d(enc, &am, A, 512);

    cudaFuncSetAttribute(lokr_gemm, cudaFuncAttributeMaxDynamicSharedMemorySize, SMEM_BYTES);

    // Keep ncu (-s 5 -c 1) landing on the GEMM.
    dummy_k<<<1, 1>>>();
    dummy_k<<<1, 1>>>();
    prep_x<<<256, 256>>>(x);
    lokr_gemm<<<136, 544, SMEM_BYTES>>>(wm, am, (float*)d_out);
    lokr_combine<<<1024, 256>>>(B, sc, (float*)d_out);
}